// round 5
// baseline (speedup 1.0000x reference)
#include <cuda_runtime.h>
#include <cstdint>

#define NMAX 100352
#define D 512
#define H 16
#define GBLK 256      // rows per CTA in gemm1 (128 threads x 2 rows)
#define CHUNK 16      // k-chunk (floats) = 64 B/row = 4 x 16B granules
#define NCHUNK (D / CHUNK)   // 32
#define NSTAGE 4

__device__ __align__(256) float g_h[NMAX * H];
__device__ __align__(256) float g_agg[NMAX * H];

// ---------------------------------------------------------------------------
// f32x2 packed helpers
// ---------------------------------------------------------------------------
__device__ __forceinline__ unsigned long long pk2(float lo, float hi) {
    unsigned long long r;
    asm("mov.b64 %0, {%1, %2};" : "=l"(r) : "f"(lo), "f"(hi));
    return r;
}
__device__ __forceinline__ void unpk2(unsigned long long v, float& lo, float& hi) {
    asm("mov.b64 {%0, %1}, %2;" : "=f"(lo), "=f"(hi) : "l"(v));
}
__device__ __forceinline__ void fma2(unsigned long long& acc,
                                     unsigned long long a, unsigned long long b) {
    asm("fma.rn.f32x2 %0, %1, %2, %0;" : "+l"(acc) : "l"(a), "l"(b));
}
__device__ __forceinline__ unsigned int smem_u32(const void* p) {
    unsigned int a;
    asm("{ .reg .u64 t; cvta.to.shared.u64 t, %1; cvt.u32.u64 %0, t; }"
        : "=r"(a) : "l"(p));
    return a;
}
__device__ __forceinline__ void cp16(unsigned int dst, const void* src) {
    asm volatile("cp.async.cg.shared.global [%0], [%1], 16;" :: "r"(dst), "l"(src));
}

// ---------------------------------------------------------------------------
// Kernel 1: h0 = X @ W1 (also zeros g_agg rows).
// 4-stage cp.async ring (3 chunks in flight -> DRAM latency absorbed),
// CHUNK=16, W1 prefetched one chunk ahead into regs + double-buffered smem.
// XOR swizzle for 64B rows: granule q ^ ((row>>1)&3) -> conflict-free LDS.128.
// ---------------------------------------------------------------------------
__global__ void __launch_bounds__(128) gemm1_kernel(
    const float* __restrict__ x, const float* __restrict__ W1, int N)
{
    __shared__ __align__(16) float4 xbuf[NSTAGE][GBLK * 4];  // 4 x 16 KB
    __shared__ __align__(16) float  wbuf[2][CHUNK * 16 * 2]; // 2 x 2 KB packed (w,w)

    const int tid  = threadIdx.x;
    const int row0 = blockIdx.x * GBLK;
    const unsigned int xb_addr = smem_u32(xbuf);

    unsigned long long acc[16];   // pair = (row tid, row tid+128)
#pragma unroll
    for (int c = 0; c < 16; c++) acc[c] = 0ull;

    // stage chunk `ch` into ring slot ch&3
    auto stage = [&](int ch) {
        const int buf = ch & (NSTAGE - 1);
#pragma unroll
        for (int i = 0; i < 8; i++) {
            int g   = i * 128 + tid;            // 0..1023 granules
            int row = g >> 2;
            int q   = g & 3;
            int grow = row0 + row;
            unsigned int dst = xb_addr +
                ((unsigned)(buf * GBLK * 4 + row * 4 + (q ^ ((row >> 1) & 3)))) * 16u;
            const float* src = x + (size_t)grow * D + ch * CHUNK + q * 4;
            if (grow < N) cp16(dst, src);
        }
        asm volatile("cp.async.commit_group;");
    };

    // W prefetch: w_next holds chunk (ch+1)'s 2 floats for this thread
    auto ldw = [&](int ch) -> float2 {
        return ((const float2*)(W1 + ch * CHUNK * 16))[tid];
    };
    auto stw = [&](float2 w, int buf) {
        float2* wp = (float2*)wbuf[buf];
        wp[tid * 2 + 0] = make_float2(w.x, w.x);
        wp[tid * 2 + 1] = make_float2(w.y, w.y);
    };

    // prologue: 3 chunks in flight, W0 in smem, W1 in regs
    stage(0); stage(1); stage(2);
    stw(ldw(0), 0);
    float2 w_next = ldw(1);

    const int sw = (tid >> 1) & 3;

    for (int ch = 0; ch < NCHUNK; ch++) {
        const int cur = ch & (NSTAGE - 1);
        if (ch + 3 < NCHUNK) stage(ch + 3);
        // W for ch+1 into the other wbuf (its last reader synced at end of ch-1)
        if (ch + 1 < NCHUNK) stw(w_next, (ch + 1) & 1);
        if (ch + 2 < NCHUNK) w_next = ldw(ch + 2);

        if (ch < NCHUNK - 3) asm volatile("cp.async.wait_group %0;" :: "n"(3));
        else                 asm volatile("cp.async.wait_group 0;");
        __syncthreads();

        const float4* xb = xbuf[cur];
        const float*  wb = wbuf[ch & 1];
#pragma unroll
        for (int kg = 0; kg < 4; kg++) {
            float4 a0 = xb[tid * 4 + (kg ^ sw)];
            float4 a1 = xb[(tid + 128) * 4 + (kg ^ sw)];
            float a0v[4] = {a0.x, a0.y, a0.z, a0.w};
            float a1v[4] = {a1.x, a1.y, a1.z, a1.w};
#pragma unroll
            for (int j = 0; j < 4; j++) {
                int k = kg * 4 + j;
                unsigned long long p = pk2(a0v[j], a1v[j]);
                const ulonglong2* wp = (const ulonglong2*)(wb + k * 32);
#pragma unroll
                for (int cp = 0; cp < 8; cp++) {
                    ulonglong2 w2 = wp[cp];
                    fma2(acc[cp * 2 + 0], p, w2.x);
                    fma2(acc[cp * 2 + 1], p, w2.y);
                }
            }
        }
        __syncthreads();   // protect xbuf slot reused by stage(ch+4) & wbuf writes
    }

    // epilogue: write h rows + zero agg rows
    const float4 z4 = make_float4(0.f, 0.f, 0.f, 0.f);
#pragma unroll
    for (int pr = 0; pr < 2; pr++) {
        int r = row0 + tid + pr * 128;
        if (r >= N) continue;
        float out[16];
#pragma unroll
        for (int c = 0; c < 16; c++) {
            float lo, hi;
            unpk2(acc[c], lo, hi);
            out[c] = pr ? hi : lo;
        }
        float4* hp = (float4*)(g_h + (size_t)r * H);
        float4* ap = (float4*)(g_agg + (size_t)r * H);
#pragma unroll
        for (int q = 0; q < 4; q++) {
            hp[q] = make_float4(out[q*4+0], out[q*4+1], out[q*4+2], out[q*4+3]);
            ap[q] = z4;
        }
    }
}

// ---------------------------------------------------------------------------
// Kernel 2: edge scatter  agg[dst] += w * h[src]
// 4 lanes per edge: one LDG.128 + one red.v4 per lane.
// ---------------------------------------------------------------------------
__device__ __forceinline__ void red4(float* p, float a, float b, float c, float d) {
    asm volatile("red.global.add.v4.f32 [%0], {%1, %2, %3, %4};"
                 :: "l"(p), "f"(a), "f"(b), "f"(c), "f"(d) : "memory");
}

__global__ void __launch_bounds__(256) scatter_kernel(
    const int* __restrict__ ei, const float* __restrict__ ew, int E)
{
    int t = blockIdx.x * 256 + threadIdx.x;
    int e = t >> 2;
    if (e >= E) return;
    int q = t & 3;

    int   s = __ldg(ei + e);
    int   d = __ldg(ei + (size_t)E + e);
    float w = __ldg(ew + e);

    float4 v = *(const float4*)(g_h + (size_t)s * H + q * 4);
    red4(g_agg + (size_t)d * H + q * 4, w * v.x, w * v.y, w * v.z, w * v.w);
}

// ---------------------------------------------------------------------------
// Kernel 3: h1 = relu(agg + b1); h2pre = h1 @ W2 -> g_h; re-zero g_agg row
// ---------------------------------------------------------------------------
__global__ void __launch_bounds__(256) layer2_kernel(
    const float* __restrict__ b1, const float* __restrict__ W2, int N)
{
    __shared__ float W2s[256];
    __shared__ float b1s[16];
    int tid = threadIdx.x;
    W2s[tid] = W2[tid];
    if (tid < 16) b1s[tid] = b1[tid];
    __syncthreads();

    int n = blockIdx.x * 256 + tid;
    if (n >= N) return;

    float h[16];
    const float4* ap = (const float4*)(g_agg + (size_t)n * H);
#pragma unroll
    for (int q = 0; q < 4; q++) *(float4*)(h + 4 * q) = ap[q];
#pragma unroll
    for (int k = 0; k < 16; k++) h[k] = fmaxf(h[k] + b1s[k], 0.f);

    float o[16];
#pragma unroll
    for (int c = 0; c < 16; c++) o[c] = 0.f;
#pragma unroll
    for (int k = 0; k < 16; k++) {
        float hv = h[k];
#pragma unroll
        for (int q = 0; q < 4; q++) {
            float4 w = *(const float4*)(W2s + k * 16 + q * 4);
            o[q*4+0] += hv * w.x; o[q*4+1] += hv * w.y;
            o[q*4+2] += hv * w.z; o[q*4+3] += hv * w.w;
        }
    }

    float4* hp = (float4*)(g_h + (size_t)n * H);
    float4* az = (float4*)(g_agg + (size_t)n * H);
    const float4 z4 = make_float4(0.f, 0.f, 0.f, 0.f);
#pragma unroll
    for (int q = 0; q < 4; q++) {
        hp[q] = make_float4(o[q*4+0], o[q*4+1], o[q*4+2], o[q*4+3]);
        az[q] = z4;
    }
}

// ---------------------------------------------------------------------------
// Kernel 4: out = log_softmax(agg + b2)
// ---------------------------------------------------------------------------
__global__ void __launch_bounds__(256) final_kernel(
    const float* __restrict__ b2, float* __restrict__ out, int N)
{
    __shared__ float b2s[16];
    int tid = threadIdx.x;
    if (tid < 16) b2s[tid] = b2[tid];
    __syncthreads();

    int n = blockIdx.x * 256 + tid;
    if (n >= N) return;

    float v[16];
    const float4* ap = (const float4*)(g_agg + (size_t)n * H);
#pragma unroll
    for (int q = 0; q < 4; q++) *(float4*)(v + 4 * q) = ap[q];
#pragma unroll
    for (int k = 0; k < 16; k++) v[k] += b2s[k];

    float m = v[0];
#pragma unroll
    for (int k = 1; k < 16; k++) m = fmaxf(m, v[k]);
    float s = 0.f;
#pragma unroll
    for (int k = 0; k < 16; k++) s += expf(v[k] - m);
    float l = logf(s) + m;

    float4* op = (float4*)(out + (size_t)n * H);
#pragma unroll
    for (int q = 0; q < 4; q++)
        op[q] = make_float4(v[q*4+0] - l, v[q*4+1] - l, v[q*4+2] - l, v[q*4+3] - l);
}

// ---------------------------------------------------------------------------
extern "C" void kernel_launch(void* const* d_in, const int* in_sizes, int n_in,
                              void* d_out, int out_size)
{
    const float* x  = (const float*)d_in[0];
    const int*   ei = (const int*)d_in[1];
    const float* ew = (const float*)d_in[2];
    const float* W1 = (const float*)d_in[3];
    const float* b1 = (const float*)d_in[4];
    const float* W2 = (const float*)d_in[5];
    const float* b2 = (const float*)d_in[6];
    float* out = (float*)d_out;

    int N = in_sizes[0] / D;      // 100000
    int E = in_sizes[2];          // 3200000

    int nblk = (N + 255) / 256;
    int gblk = (N + GBLK - 1) / GBLK;
    int eblk = ((E * 4) + 255) / 256;   // 4 lanes per edge

    gemm1_kernel<<<gblk, 128>>>(x, W1, N);
    scatter_kernel<<<eblk, 256>>>(ei, ew, E);
    layer2_kernel<<<nblk, 256>>>(b1, W2, N);
    scatter_kernel<<<eblk, 256>>>(ei, ew, E);
    final_kernel<<<nblk, 256>>>(b2, out, N);
}